// round 6
// baseline (speedup 1.0000x reference)
#include <cuda_runtime.h>

// Problem constants (fixed by the dataset: B=4, N=1e6, H=W=128)
#define BATCH 4
#define NEV   1000000
#define HDIM  128
#define WDIM  128
#define HW    (HDIM * WDIM)

#define CTAS_PER_BATCH 37
#define GRID_SCATTER   (BATCH * CTAS_PER_BATCH)          // 148 = one CTA per SM
#define EV_PER_CTA     ((NEV + CTAS_PER_BATCH - 1) / CTAS_PER_BATCH)  // 27028
#define SMEM_BYTES     (HW * sizeof(float2))             // 128 KB

// Kernel 1: write avg_flow channels (2,3) and zero the IWE channels (0,1).
__global__ void init_out_kernel(const float* __restrict__ flow,
                                const float* __restrict__ event_mask,
                                float* __restrict__ out) {
    int i = blockIdx.x * blockDim.x + threadIdx.x;   // over BATCH*HW
    if (i >= BATCH * HW) return;
    int b = i / HW;
    int p = i - b * HW;

    float m = event_mask[i];
    float s = m / (m + 1e-9f);               // exact same arithmetic as ref

    const float* fb = flow + (size_t)b * 2 * HW;
    float* ob = out + (size_t)b * 4 * HW;

    ob[p]          = 0.0f;                   // iwe_pos
    ob[HW + p]     = 0.0f;                   // iwe_neg
    ob[2 * HW + p] = fb[p]      * s;         // avg_flow ch0
    ob[3 * HW + p] = fb[HW + p] * s;         // avg_flow ch1
}

// Vector global reductions (fire-and-forget, no return value).
__device__ __forceinline__ void red_v4(float* p, float a, float b, float c, float d) {
    asm volatile("red.global.add.v4.f32 [%0], {%1, %2, %3, %4};"
                 :: "l"(p), "f"(a), "f"(b), "f"(c), "f"(d) : "memory");
}
__device__ __forceinline__ void red_v2(float* p, float a, float b) {
    asm volatile("red.global.add.v2.f32 [%0], {%1, %2};"
                 :: "l"(p), "f"(a), "f"(b) : "memory");
}

// Emit the two x-corners (columns lx, lx+1) of one valid row.
// Fast path (lx in [0,126], ~both corners in-bounds): branch only on lx&3,
// no zero-weight checks (adding 0.0f is an exact no-op).
__device__ __forceinline__ void emit_row(float* rowp, int lx, float wl, float wr) {
    if ((unsigned)lx <= (unsigned)(WDIM - 2)) {      // 0 <= lx <= 126
        int s = lx & 3;
        if ((s & 1) == 0) {
            red_v2(rowp + lx, wl, wr);               // 8B-aligned pair (s=0,2)
        } else if (s == 1) {
            red_v4(rowp + lx - 1, 0.0f, wl, wr, 0.0f);
        } else {                                     // s == 3: straddles 16B
            atomicAdd(rowp + lx, wl);
            atomicAdd(rowp + lx + 1, wr);
        }
    } else if (lx == -1) {
        if (wr != 0.0f) atomicAdd(rowp, wr);         // only right corner valid
    } else if (lx == WDIM - 1) {
        if (wl != 0.0f) atomicAdd(rowp + lx, wl);    // only left corner valid
    }
    // else: both columns OOB -> nothing (ref scatters weight 0 into bin 0)
}

// Kernel 2: batch-partitioned scatter with flow staged in shared memory.
// 148 CTAs (one wave), 37 per batch, 1024 threads each.
__global__ __launch_bounds__(1024, 1)
void scatter_kernel(const float4* __restrict__ ev,   // [B*N] (ts,y,x,p)
                    const float* __restrict__ flow,  // [B,2,H,W]
                    float* __restrict__ out) {       // [B,4,H,W]
    extern __shared__ float2 sflow[];                // [HW] = 128 KB

    int b = blockIdx.x / CTAS_PER_BATCH;
    int c = blockIdx.x - b * CTAS_PER_BATCH;

    // Stage this batch's flow, interleaved (fx, fy), via coalesced float4 loads.
    const float4* fx4 = (const float4*)(flow + (size_t)b * 2 * HW);
    const float4* fy4 = (const float4*)(flow + (size_t)b * 2 * HW + HW);
    for (int i = threadIdx.x; i < HW / 4; i += blockDim.x) {
        float4 a = fx4[i];
        float4 d = fy4[i];
        sflow[4 * i + 0] = make_float2(a.x, d.x);
        sflow[4 * i + 1] = make_float2(a.y, d.y);
        sflow[4 * i + 2] = make_float2(a.z, d.z);
        sflow[4 * i + 3] = make_float2(a.w, d.w);
    }
    __syncthreads();

    const float4* evb = ev + (size_t)b * NEV;
    float* ob = out + (size_t)b * 4 * HW;

    int e0 = c * EV_PER_CTA;
    int e1 = e0 + EV_PER_CTA; if (e1 > NEV) e1 = NEV;

    #pragma unroll 4
    for (int i = e0 + threadIdx.x; i < e1; i += blockDim.x) {
        float4 e = evb[i];
        float ts = e.x, y = e.y, x = e.z, p = e.w;

        // flow_idx = round(y)*W + round(x); y,x are integer-valued -> exact
        int gidx = __float2int_rn(y) * WDIM + __float2int_rn(x);
        float2 f = sflow[gidx];                  // (ef_x, ef_y), one LDS.64

        float dt = 1.0f - ts;
        float wy = fmaf(dt, f.y, y);
        float wx = fmaf(dt, f.x, x);

        float tyf = floorf(wy);
        float lxf = floorf(wx);
        float fy = wy - tyf;
        float fx = wx - lxf;

        int ty = (int)tyf;
        int lx = (int)lxf;
        int by = ty + 1;

        // pol_mask = (p, 1-p), p in {0,1}: each event hits exactly one channel
        float* base = ob + ((p > 0.5f) ? 0 : HW);

        float w_b = fy, w_t = 1.0f - fy;
        float w_r = fx, w_l = 1.0f - fx;

        if ((unsigned)ty < (unsigned)HDIM)
            emit_row(base + ty * WDIM, lx, w_t * w_l, w_t * w_r);
        if ((unsigned)by < (unsigned)HDIM)
            emit_row(base + by * WDIM, lx, w_b * w_l, w_b * w_r);
    }
}

extern "C" void kernel_launch(void* const* d_in, const int* in_sizes, int n_in,
                              void* d_out, int out_size) {
    const float* flow       = (const float*)d_in[0];   // [B,2,H,W]
    const float* event_list = (const float*)d_in[1];   // [B,N,4]
    // d_in[2] (pol_mask) intentionally unused: pol_mask == (p, 1-p) from event_list
    const float* event_mask = (const float*)d_in[3];   // [B,1,H,W]
    float* out = (float*)d_out;                        // [B,4,H,W]

    // Idempotent, non-syncing host-side config (no static guard: kernel_launch
    // must be stateless and deterministic).
    cudaFuncSetAttribute(scatter_kernel,
                         cudaFuncAttributeMaxDynamicSharedMemorySize, SMEM_BYTES);

    {
        int n = BATCH * HW;
        int threads = 256;
        init_out_kernel<<<(n + threads - 1) / threads, threads>>>(flow, event_mask, out);
    }
    scatter_kernel<<<GRID_SCATTER, 1024, SMEM_BYTES>>>(
        (const float4*)event_list, flow, out);
}

// round 11
// speedup vs baseline: 1.0112x; 1.0112x over previous
#include <cuda_runtime.h>

// Problem constants (fixed by the dataset: B=4, N=1e6, H=W=128)
#define BATCH 4
#define NEV   1000000
#define HDIM  128
#define WDIM  128
#define HW    (HDIM * WDIM)

#define HALF_ROWS 64                                   // rows 0..63 live in smem
#define SMEM_BYTES (HALF_ROWS * WDIM * sizeof(float2)) // 64 KB

#define CTAS_PER_BATCH 74
#define GRID_SCATTER   (BATCH * CTAS_PER_BATCH)        // 296 = 2 CTAs per SM
#define EV_PER_CTA     ((NEV + CTAS_PER_BATCH - 1) / CTAS_PER_BATCH)  // 13514

// Interleaved flow scratch: g_flow_i[b*HW + p] = (flow_x, flow_y) at pixel p.
__device__ float2 g_flow_i[BATCH * HW];

// Kernel 1: write avg_flow channels (2,3), zero the IWE channels (0,1),
// and build the interleaved flow scratch.
__global__ void init_out_kernel(const float* __restrict__ flow,
                                const float* __restrict__ event_mask,
                                float* __restrict__ out) {
    int i = blockIdx.x * blockDim.x + threadIdx.x;   // over BATCH*HW
    if (i >= BATCH * HW) return;
    int b = i / HW;
    int p = i - b * HW;

    float m = event_mask[i];
    float s = m / (m + 1e-9f);               // exact same arithmetic as ref

    const float* fb = flow + (size_t)b * 2 * HW;
    float fx = fb[p];
    float fy = fb[HW + p];
    g_flow_i[i] = make_float2(fx, fy);

    float* ob = out + (size_t)b * 4 * HW;
    ob[p]          = 0.0f;                   // iwe_pos
    ob[HW + p]     = 0.0f;                   // iwe_neg
    ob[2 * HW + p] = fx * s;                 // avg_flow ch0
    ob[3 * HW + p] = fy * s;                 // avg_flow ch1
}

// Vector global reductions (fire-and-forget, no return value).
__device__ __forceinline__ void red_v4(float* p, float a, float b, float c, float d) {
    asm volatile("red.global.add.v4.f32 [%0], {%1, %2, %3, %4};"
                 :: "l"(p), "f"(a), "f"(b), "f"(c), "f"(d) : "memory");
}
__device__ __forceinline__ void red_v2(float* p, float a, float b) {
    asm volatile("red.global.add.v2.f32 [%0], {%1, %2};"
                 :: "l"(p), "f"(a), "f"(b) : "memory");
}

// Emit the two x-corners (columns lx, lx+1) of one valid row.
__device__ __forceinline__ void emit_row(float* rowp, int lx, float wl, float wr) {
    if ((unsigned)lx <= (unsigned)(WDIM - 2)) {      // 0 <= lx <= 126
        int s = lx & 3;
        if ((s & 1) == 0) {
            red_v2(rowp + lx, wl, wr);               // 8B-aligned pair (s=0,2)
        } else if (s == 1) {
            red_v4(rowp + lx - 1, 0.0f, wl, wr, 0.0f);
        } else {                                     // s == 3: straddles 16B
            atomicAdd(rowp + lx, wl);
            atomicAdd(rowp + lx + 1, wr);
        }
    } else if (lx == -1) {
        if (wr != 0.0f) atomicAdd(rowp, wr);         // only right corner valid
    } else if (lx == WDIM - 1) {
        if (wl != 0.0f) atomicAdd(rowp + lx, wl);    // only left corner valid
    }
    // else: both columns OOB -> nothing
}

// Kernel 2: scatter. 296 CTAs (2/SM, 64 warps/SM), flow rows 0..63 in smem,
// rows 64..127 gathered from L1-resident g_flow_i.
__global__ __launch_bounds__(1024, 2)
void scatter_kernel(const float4* __restrict__ ev,   // [B*N] (ts,y,x,p)
                    float* __restrict__ out) {       // [B,4,H,W]
    extern __shared__ float2 sflow[];                // [HALF_ROWS*WDIM] = 64 KB

    int b = blockIdx.x / CTAS_PER_BATCH;
    int c = blockIdx.x - b * CTAS_PER_BATCH;

    // Stage lower-half flow (already interleaved) via coalesced 16B loads.
    {
        const float4* src = (const float4*)(g_flow_i + (size_t)b * HW);
        float4* dst = (float4*)sflow;
        for (int i = threadIdx.x; i < (HALF_ROWS * WDIM) / 2; i += blockDim.x)
            dst[i] = src[i];
    }
    __syncthreads();

    const float4* evb = ev + (size_t)b * NEV;
    float* ob = out + (size_t)b * 4 * HW;
    const float2* gup = g_flow_i + (size_t)b * HW;   // upper half via L1

    int e0 = c * EV_PER_CTA;
    int e1 = e0 + EV_PER_CTA; if (e1 > NEV) e1 = NEV;

    for (int i = e0 + threadIdx.x; i < e1; i += blockDim.x) {
        float4 e = evb[i];

        // flow_idx = round(y)*W + round(x); y,x are integer-valued -> exact
        int gidx = __float2int_rn(e.y) * WDIM + __float2int_rn(e.z);
        float2 f = (gidx < HALF_ROWS * WDIM) ? sflow[gidx] : __ldg(gup + gidx);

        float dt = 1.0f - e.x;
        float wy = fmaf(dt, f.y, e.y);
        float wx = fmaf(dt, f.x, e.z);

        float tyf = floorf(wy);
        float lxf = floorf(wx);
        float fy = wy - tyf;
        float fx = wx - lxf;

        int ty = (int)tyf;
        int lx = (int)lxf;

        // pol_mask = (p, 1-p), p in {0,1}: each event hits exactly one channel
        float* base = ob + ((e.w > 0.5f) ? 0 : HW);

        if ((unsigned)ty < (unsigned)HDIM)
            emit_row(base + ty * WDIM, lx, (1.0f - fy) * (1.0f - fx), (1.0f - fy) * fx);
        int by = ty + 1;
        if ((unsigned)by < (unsigned)HDIM)
            emit_row(base + by * WDIM, lx, fy * (1.0f - fx), fy * fx);
    }
}

extern "C" void kernel_launch(void* const* d_in, const int* in_sizes, int n_in,
                              void* d_out, int out_size) {
    const float* flow       = (const float*)d_in[0];   // [B,2,H,W]
    const float* event_list = (const float*)d_in[1];   // [B,N,4]
    // d_in[2] (pol_mask) intentionally unused: pol_mask == (p, 1-p) from event_list
    const float* event_mask = (const float*)d_in[3];   // [B,1,H,W]
    float* out = (float*)d_out;                        // [B,4,H,W]

    // Idempotent, non-syncing host-side config (stateless kernel_launch).
    cudaFuncSetAttribute(scatter_kernel,
                         cudaFuncAttributeMaxDynamicSharedMemorySize, SMEM_BYTES);

    {
        int n = BATCH * HW;
        int threads = 256;
        init_out_kernel<<<(n + threads - 1) / threads, threads>>>(flow, event_mask, out);
    }
    scatter_kernel<<<GRID_SCATTER, 1024, SMEM_BYTES>>>(
        (const float4*)event_list, out);
}

// round 13
// speedup vs baseline: 2.1387x; 2.1151x over previous
#include <cuda_runtime.h>

// Problem constants (fixed by the dataset: B=4, N=1e6, H=W=128)
#define BATCH 4
#define NEV   1000000
#define HDIM  128
#define WDIM  128
#define HW    (HDIM * WDIM)

#define HALF_ROWS 64                                   // flow rows 0..63 in smem
#define SMEM_BYTES (HALF_ROWS * WDIM * sizeof(float2)) // 64 KB

#define CTAS_PER_BATCH 74
#define GRID_SCATTER   (BATCH * CTAS_PER_BATCH)        // 296 = 2 CTAs per SM
#define EV_PER_CTA     ((NEV + CTAS_PER_BATCH - 1) / CTAS_PER_BATCH)  // 13514

// Quad-interleaved scatter scratch.
// 4 staggered copies (dy,dx in {0,1}^2). Copy c=(dy*2+dx) stores pixel (y,x) of
// (b,ch) at quad (qy,qx) = ((y+dy)>>1, (x+dx)>>1), sub-slot (u&1)*2+(v&1) with
// u=y+dy, v=x+dx. A 2x2 bilinear box whose top-left (ty,lx) satisfies
// (ty+dy) even, (lx+dx) even occupies ONE aligned float4 -> one red.v4.
// Quad grid is 65x65 so ghost rows/cols u,v in {0|129} (image y,x = -1|128)
// have slots that the gather pass never reads -> no bounds masking needed.
#define QDIM 65
#define SCRATCH_F4 (4 * BATCH * 2 * QDIM * QDIM)       // 135200 float4 = 2.11 MB
__device__ float4 g_scratch[SCRATCH_F4];

// Interleaved flow scratch: g_flow_i[b*HW + p] = (flow_x, flow_y) at pixel p.
__device__ float2 g_flow_i[BATCH * HW];

// Kernel 1: avg_flow channels (2,3), interleaved flow map, zero quad scratch.
// (IWE channels 0,1 are fully overwritten by the gather kernel -> no zeroing.)
__global__ void init_kernel(const float* __restrict__ flow,
                            const float* __restrict__ event_mask,
                            float* __restrict__ out) {
    int i = blockIdx.x * blockDim.x + threadIdx.x;   // over BATCH*HW = 65536
    if (i < BATCH * HW) {
        int b = i / HW;
        int p = i - b * HW;

        float m = event_mask[i];
        float s = m / (m + 1e-9f);           // exact same arithmetic as ref

        const float* fb = flow + (size_t)b * 2 * HW;
        float fx = fb[p];
        float fy = fb[HW + p];
        g_flow_i[i] = make_float2(fx, fy);

        float* ob = out + (size_t)b * 4 * HW;
        ob[2 * HW + p] = fx * s;             // avg_flow ch0
        ob[3 * HW + p] = fy * s;             // avg_flow ch1
    }
    // Zero the quad scratch (grid-stride; ~2 float4 per thread).
    for (int j = i; j < SCRATCH_F4; j += BATCH * HW)
        g_scratch[j] = make_float4(0.0f, 0.0f, 0.0f, 0.0f);
}

// One aligned 16B global reduction (fire-and-forget).
__device__ __forceinline__ void red_v4(float4* p, float a, float b, float c, float d) {
    asm volatile("red.global.add.v4.f32 [%0], {%1, %2, %3, %4};"
                 :: "l"(p), "f"(a), "f"(b), "f"(c), "f"(d) : "memory");
}

// Kernel 2: scatter. 296 CTAs (2/SM), flow rows 0..63 in smem, rows 64..127
// via L1-resident g_flow_i. Exactly ONE red.v4 per (not fully OOB) event.
__global__ __launch_bounds__(1024, 2)
void scatter_kernel(const float4* __restrict__ ev) {  // [B*N] (ts,y,x,p)
    extern __shared__ float2 sflow[];                 // 64 KB

    int b = blockIdx.x / CTAS_PER_BATCH;
    int c = blockIdx.x - b * CTAS_PER_BATCH;

    {
        const float4* src = (const float4*)(g_flow_i + (size_t)b * HW);
        float4* dst = (float4*)sflow;
        for (int i = threadIdx.x; i < (HALF_ROWS * WDIM) / 2; i += blockDim.x)
            dst[i] = src[i];
    }
    __syncthreads();

    const float4* evb = ev + (size_t)b * NEV;
    const float2* gup = g_flow_i + (size_t)b * HW;

    int e0 = c * EV_PER_CTA;
    int e1 = e0 + EV_PER_CTA; if (e1 > NEV) e1 = NEV;

    for (int i = e0 + threadIdx.x; i < e1; i += blockDim.x) {
        float4 e = evb[i];

        // flow_idx = round(y)*W + round(x); y,x are integer-valued -> exact
        int gidx = __float2int_rn(e.y) * WDIM + __float2int_rn(e.z);
        float2 f = (gidx < HALF_ROWS * WDIM) ? sflow[gidx] : __ldg(gup + gidx);

        float dt = 1.0f - e.x;
        float wy = fmaf(dt, f.y, e.y);
        float wx = fmaf(dt, f.x, e.z);

        float tyf = floorf(wy);
        float lxf = floorf(wx);
        float fy = wy - tyf;                 // in [0,1)
        float fx = wx - lxf;

        int ty = (int)tyf;
        int lx = (int)lxf;

        // Skip only if NO corner can be in-bounds. Partially-OOB corners land
        // in ghost scratch slots that the gather never reads.
        if ((unsigned)(ty + 1) > 128u || (unsigned)(lx + 1) > 128u) continue;

        int dy = ty & 1;                     // works for ty = -1 too
        int dx = lx & 1;
        int qy = (ty + dy) >> 1;             // in [0,64]
        int qx = (lx + dx) >> 1;
        int ch = (e.w > 0.5f) ? 0 : 1;       // pol_mask == (p, 1-p)
        int copy = dy * 2 + dx;

        int slot = (((copy * BATCH + b) * 2 + ch) * QDIM + qy) * QDIM + qx;

        float wt = 1.0f - fy, wb = fy;
        float wl = 1.0f - fx, wr = fx;
        // sub-slots: 0=(top,left) 1=(top,right) 2=(bot,left) 3=(bot,right)
        red_v4(&g_scratch[slot], wt * wl, wt * wr, wb * wl, wb * wr);
    }
}

// Kernel 3: gather the 4 staggered copies into the IWE output channels.
__global__ void gather_kernel(float* __restrict__ out) {
    int i = blockIdx.x * blockDim.x + threadIdx.x;   // over BATCH*HW
    if (i >= BATCH * HW) return;
    int b = i / HW;
    int p = i - b * HW;
    int y = p >> 7;
    int x = p & (WDIM - 1);

    float acc0 = 0.0f, acc1 = 0.0f;
    #pragma unroll
    for (int dy = 0; dy < 2; dy++) {
        #pragma unroll
        for (int dx = 0; dx < 2; dx++) {
            int u = y + dy, v = x + dx;
            int qy = u >> 1, qx = v >> 1;
            int o = (u & 1) * 2 + (v & 1);
            int copy = dy * 2 + dx;
            int s0 = (((copy * BATCH + b) * 2 + 0) * QDIM + qy) * QDIM + qx;
            int s1 = (((copy * BATCH + b) * 2 + 1) * QDIM + qy) * QDIM + qx;
            acc0 += ((const float*)&g_scratch[s0])[o];
            acc1 += ((const float*)&g_scratch[s1])[o];
        }
    }
    float* ob = out + (size_t)b * 4 * HW;
    ob[p]      = acc0;                       // iwe_pos
    ob[HW + p] = acc1;                       // iwe_neg
}

extern "C" void kernel_launch(void* const* d_in, const int* in_sizes, int n_in,
                              void* d_out, int out_size) {
    const float* flow       = (const float*)d_in[0];   // [B,2,H,W]
    const float* event_list = (const float*)d_in[1];   // [B,N,4]
    // d_in[2] (pol_mask) intentionally unused: pol_mask == (p, 1-p) from event_list
    const float* event_mask = (const float*)d_in[3];   // [B,1,H,W]
    float* out = (float*)d_out;                        // [B,4,H,W]

    // Idempotent, non-syncing host-side config (stateless kernel_launch).
    cudaFuncSetAttribute(scatter_kernel,
                         cudaFuncAttributeMaxDynamicSharedMemorySize, SMEM_BYTES);

    {
        int n = BATCH * HW;
        init_kernel<<<(n + 255) / 256, 256>>>(flow, event_mask, out);
    }
    scatter_kernel<<<GRID_SCATTER, 1024, SMEM_BYTES>>>((const float4*)event_list);
    {
        int n = BATCH * HW;
        gather_kernel<<<(n + 255) / 256, 256>>>(out);
    }
}